// round 2
// baseline (speedup 1.0000x reference)
#include <cuda_runtime.h>
#include <math.h>

// Problem constants (fixed shapes)
#define N_TOK 16384          // B*S = 4*4096
#define DIM   768
#define NEXP  8
#define TOPK  2
#define HID   2048
#define CAP   5120           // ceil(1.25 * 2 * 16384 / 8)
#define NK    (N_TOK*TOPK)   // 32768
#define NSLOT (NEXP*CAP)     // 40960

// ---------------- device scratch (static globals; no allocation) ----------------
__device__ int   g_topk_e[NK];
__device__ float g_topk_w[NK];
__device__ int   g_assign_slot[NK];   // slot id per assignment, -1 if dropped
__device__ int   g_count[NEXP];       // min(total, CAP) per expert
__device__ int   g_slot_token[NSLOT]; // token index per slot
__device__ float g_z[(size_t)NSLOT*DIM];   // RMSNorm'd activations
__device__ float g_h[(size_t)NSLOT*HID];   // silu(g)*u
__device__ float g_y[(size_t)NSLOT*DIM];   // x + down-proj

// ---------------- router: logits, top-2, renormalized weights ----------------
__global__ __launch_bounds__(256) void router_kernel(const float* __restrict__ x,
                                                     const float* __restrict__ gate_w) {
    __shared__ float gw[NEXP*DIM];
    int t = threadIdx.x;
    for (int i = t; i < NEXP*DIM; i += 256) gw[i] = gate_w[i];
    __syncthreads();

    int warp = t >> 5, lane = t & 31;
    int token = blockIdx.x * 8 + warp;
    const float* xr = x + (size_t)token * DIM;

    float acc[NEXP];
    #pragma unroll
    for (int e = 0; e < NEXP; e++) acc[e] = 0.f;
    #pragma unroll
    for (int i = 0; i < DIM/32; i++) {
        float xv = xr[lane + 32*i];
        #pragma unroll
        for (int e = 0; e < NEXP; e++) acc[e] += xv * gw[e*DIM + lane + 32*i];
    }
    #pragma unroll
    for (int e = 0; e < NEXP; e++) {
        #pragma unroll
        for (int off = 16; off; off >>= 1)
            acc[e] += __shfl_xor_sync(0xffffffffu, acc[e], off);
    }
    if (lane == 0) {
        int i0 = 0;
        #pragma unroll
        for (int e = 1; e < NEXP; e++) if (acc[e] > acc[i0]) i0 = e;
        int i1 = -1;
        #pragma unroll
        for (int e = 0; e < NEXP; e++) {
            if (e == i0) continue;
            if (i1 < 0 || acc[e] > acc[i1]) i1 = e;
        }
        float l0 = acc[i0], l1 = acc[i1];
        // renormalized top-2 softmax weights: denom cancels
        float w0 = 1.f / (1.f + expf(l1 - l0));
        float w1 = 1.f / (1.f + expf(l0 - l1));
        g_topk_e[2*token]   = i0;  g_topk_e[2*token+1] = i1;
        g_topk_w[2*token]   = w0;  g_topk_w[2*token+1] = w1;
    }
}

// ---------------- dispatch: exact serial-order capacity ranking ----------------
// One block, 1024 threads; each thread owns 32 consecutive assignments.
__global__ __launch_bounds__(1024) void dispatch_kernel() {
    __shared__ int s[1024][NEXP];
    int tid = threadIdx.x;
    int base_i = tid * 32;

    int cnt[NEXP];
    #pragma unroll
    for (int e = 0; e < NEXP; e++) cnt[e] = 0;
    for (int i = 0; i < 32; i++) cnt[g_topk_e[base_i + i]]++;
    #pragma unroll
    for (int e = 0; e < NEXP; e++) s[tid][e] = cnt[e];
    __syncthreads();

    // Hillis-Steele inclusive scan over threads, per expert
    for (int off = 1; off < 1024; off <<= 1) {
        int v[NEXP];
        if (tid >= off) {
            #pragma unroll
            for (int e = 0; e < NEXP; e++) v[e] = s[tid - off][e];
        }
        __syncthreads();
        if (tid >= off) {
            #pragma unroll
            for (int e = 0; e < NEXP; e++) s[tid][e] += v[e];
        }
        __syncthreads();
    }

    int run[NEXP];
    #pragma unroll
    for (int e = 0; e < NEXP; e++) run[e] = (tid == 0) ? 0 : s[tid-1][e];
    if (tid == 0) {
        for (int e = 0; e < NEXP; e++) {
            int tot = s[1023][e];
            g_count[e] = tot < CAP ? tot : CAP;
        }
    }
    for (int i = 0; i < 32; i++) {
        int idx = base_i + i;
        int e = g_topk_e[idx];
        int pos = run[e]++;
        if (pos < CAP) {
            int slot = e * CAP + pos;
            g_slot_token[slot] = idx >> 1;
            g_assign_slot[idx] = slot;
        } else {
            g_assign_slot[idx] = -1;
        }
    }
}

// ---------------- prep: z = RMSNorm(2x) * norm_w, gathered per slot ----------------
__global__ __launch_bounds__(256) void prep_kernel(const float* __restrict__ x,
                                                   const float* __restrict__ norm_w) {
    int warp = threadIdx.x >> 5, lane = threadIdx.x & 31;
    int slot = blockIdx.x * 8 + warp;
    int e = slot / CAP, c = slot % CAP;
    if (c >= g_count[e]) return;
    int token = g_slot_token[slot];
    const float* xr = x + (size_t)token * DIM;

    float xv[DIM/32];
    float ss = 0.f;
    #pragma unroll
    for (int i = 0; i < DIM/32; i++) {
        xv[i] = xr[lane + 32*i];
        ss += xv[i] * xv[i];
    }
    #pragma unroll
    for (int off = 16; off; off >>= 1) ss += __shfl_xor_sync(0xffffffffu, ss, off);
    // z = 2x; mean(z^2) = 4*mean(x^2)
    float scale = 2.f * rsqrtf(4.f * ss / (float)DIM + 1e-6f);
    float* zr = g_z + (size_t)slot * DIM;
    const float* nw = norm_w + e * DIM;
    #pragma unroll
    for (int i = 0; i < DIM/32; i++)
        zr[lane + 32*i] = xv[i] * scale * nw[lane + 32*i];
}

// ---------------- GEMM1: gu = z @ w13^T (fused gate/up), h = silu(g)*u ----------------
// Tile 64x64, BK=32 (fully coalesced 128B loads), 256 threads, 4x4 microtile.
__global__ __launch_bounds__(256) void gemm1_kernel(const float* __restrict__ w13) {
    int e = blockIdx.z;
    int count = g_count[e];
    int m0 = blockIdx.y * 64;
    if (m0 >= count) return;
    int n0 = blockIdx.x * 64;

    const float* A  = g_z + (size_t)e * CAP * DIM;
    const float* Bg = w13 + (size_t)e * 2 * HID * DIM + (size_t)n0 * DIM;
    const float* Bu = Bg + (size_t)HID * DIM;

    __shared__ float As[32][65], Bgs[32][65], Bus[32][65];
    int t = threadIdx.x;
    int tk = t & 31, tm = t >> 5;   // load mapping: 32-wide coalesced K
    int tx = t & 15, ty = t >> 4;   // compute mapping

    float accg[4][4], accu[4][4];
    #pragma unroll
    for (int i = 0; i < 4; i++)
        #pragma unroll
        for (int j = 0; j < 4; j++) { accg[i][j] = 0.f; accu[i][j] = 0.f; }

    for (int k0 = 0; k0 < DIM; k0 += 32) {
        #pragma unroll
        for (int i = 0; i < 8; i++) {
            int row = tm + 8*i;
            As [tk][row] = A [(size_t)(m0 + row) * DIM + k0 + tk];
            Bgs[tk][row] = Bg[(size_t)row * DIM + k0 + tk];
            Bus[tk][row] = Bu[(size_t)row * DIM + k0 + tk];
        }
        __syncthreads();
        #pragma unroll
        for (int kk = 0; kk < 32; kk++) {
            float a[4], bg[4], bu[4];
            #pragma unroll
            for (int i = 0; i < 4; i++) a[i] = As[kk][ty*4 + i];
            #pragma unroll
            for (int j = 0; j < 4; j++) { bg[j] = Bgs[kk][tx*4 + j]; bu[j] = Bus[kk][tx*4 + j]; }
            #pragma unroll
            for (int i = 0; i < 4; i++)
                #pragma unroll
                for (int j = 0; j < 4; j++) {
                    accg[i][j] += a[i] * bg[j];
                    accu[i][j] += a[i] * bu[j];
                }
        }
        __syncthreads();
    }

    #pragma unroll
    for (int i = 0; i < 4; i++) {
        int row = m0 + ty*4 + i;
        float4 hv;
        float* hv_p = &hv.x;
        #pragma unroll
        for (int j = 0; j < 4; j++) {
            float g = accg[i][j], u = accu[i][j];
            hv_p[j] = (g / (1.f + expf(-g))) * u;   // silu(g)*u
        }
        *(float4*)&g_h[(size_t)(e*CAP + row) * HID + n0 + tx*4] = hv;
    }
}

// ---------------- GEMM2: y = x_token + h @ w2^T ----------------
__global__ __launch_bounds__(256) void gemm2_kernel(const float* __restrict__ w2,
                                                    const float* __restrict__ x) {
    int e = blockIdx.z;
    int count = g_count[e];
    int m0 = blockIdx.y * 64;
    if (m0 >= count) return;
    int n0 = blockIdx.x * 64;

    const float* A = g_h + (size_t)e * CAP * HID;
    const float* B = w2  + (size_t)e * DIM * HID + (size_t)n0 * HID;

    __shared__ float As[32][65], Bs[32][65];
    int t = threadIdx.x;
    int tk = t & 31, tm = t >> 5;
    int tx = t & 15, ty = t >> 4;

    float acc[4][4];
    #pragma unroll
    for (int i = 0; i < 4; i++)
        #pragma unroll
        for (int j = 0; j < 4; j++) acc[i][j] = 0.f;

    for (int k0 = 0; k0 < HID; k0 += 32) {
        #pragma unroll
        for (int i = 0; i < 8; i++) {
            int row = tm + 8*i;
            As[tk][row] = A[(size_t)(m0 + row) * HID + k0 + tk];
            Bs[tk][row] = B[(size_t)row * HID + k0 + tk];
        }
        __syncthreads();
        #pragma unroll
        for (int kk = 0; kk < 32; kk++) {
            float a[4], b[4];
            #pragma unroll
            for (int i = 0; i < 4; i++) a[i] = As[kk][ty*4 + i];
            #pragma unroll
            for (int j = 0; j < 4; j++) b[j] = Bs[kk][tx*4 + j];
            #pragma unroll
            for (int i = 0; i < 4; i++)
                #pragma unroll
                for (int j = 0; j < 4; j++) acc[i][j] += a[i] * b[j];
        }
        __syncthreads();
    }

    #pragma unroll
    for (int i = 0; i < 4; i++) {
        int row = m0 + ty*4 + i;
        int slot = e * CAP + row;
        int token = g_slot_token[slot];
        int col = n0 + tx*4;
        float4 xv = *(const float4*)&x[(size_t)token * DIM + col];
        float4 yv;
        yv.x = xv.x + acc[i][0];
        yv.y = xv.y + acc[i][1];
        yv.z = xv.z + acc[i][2];
        yv.w = xv.w + acc[i][3];
        *(float4*)&g_y[(size_t)slot * DIM + col] = yv;
    }
}

// ---------------- combine: out[n,d] = sum_k cw * y[slot(n,k), d] ----------------
__global__ __launch_bounds__(256) void combine_kernel(float* __restrict__ out) {
    int idx = blockIdx.x * 256 + threadIdx.x;
    if (idx >= N_TOK * DIM) return;
    int n = idx / DIM, d = idx - n * DIM;
    float r = 0.f;
    int s0 = g_assign_slot[2*n], s1 = g_assign_slot[2*n + 1];
    if (s0 >= 0) r += g_topk_w[2*n]     * g_y[(size_t)s0 * DIM + d];
    if (s1 >= 0) r += g_topk_w[2*n + 1] * g_y[(size_t)s1 * DIM + d];
    out[idx] = r;
}

// ---------------- launch ----------------
extern "C" void kernel_launch(void* const* d_in, const int* in_sizes, int n_in,
                              void* d_out, int out_size) {
    const float* x      = (const float*)d_in[0];
    const float* gate_w = (const float*)d_in[1];
    const float* w13    = (const float*)d_in[2];
    const float* w2     = (const float*)d_in[3];
    const float* norm_w = (const float*)d_in[4];
    float* out = (float*)d_out;

    router_kernel  <<<N_TOK/8, 256>>>(x, gate_w);
    dispatch_kernel<<<1, 1024>>>();
    prep_kernel    <<<NSLOT/8, 256>>>(x, norm_w);
    gemm1_kernel   <<<dim3(HID/64, CAP/64, NEXP), 256>>>(w13);
    gemm2_kernel   <<<dim3(DIM/64, CAP/64, NEXP), 256>>>(w2, x);
    combine_kernel <<<(N_TOK*DIM + 255)/256, 256>>>(out);
}

// round 4
// speedup vs baseline: 4.0788x; 4.0788x over previous
#include <cuda_runtime.h>
#include <math.h>
#include <stdint.h>

// Problem constants
#define N_TOK 16384
#define DIM   768
#define NEXP  8
#define HID   2048
#define CAP   5120
#define NK    (N_TOK*2)
#define NSLOT (NEXP*CAP)

#define W13N (NEXP*2*HID*DIM)   // 25,165,824
#define W2N  (NEXP*DIM*HID)     // 12,582,912

// ---------------- device scratch ----------------
__device__ int   g_topk_e[NK];
__device__ float g_topk_w[NK];
__device__ int   g_assign_slot[NK];
__device__ int   g_count[NEXP];
__device__ int   g_slot_token[NSLOT];
__device__ float g_z[(size_t)NSLOT*DIM];
__device__ float g_h[(size_t)NSLOT*HID];
__device__ float g_y[(size_t)NSLOT*DIM];
__device__ float g_w13c[W13N];   // tf32-rounded weights
__device__ float g_w2c[W2N];

// ---------------- helpers ----------------
__device__ __forceinline__ uint32_t smem_u32(const void* p) {
    uint32_t a;
    asm("{ .reg .u64 t; cvta.to.shared.u64 t, %1; cvt.u32.u64 %0, t; }" : "=r"(a) : "l"(p));
    return a;
}
__device__ __forceinline__ float tf32r(float x) {
    float r; asm("cvt.rna.tf32.f32 %0, %1;" : "=f"(r) : "f"(x)); return r;
}
#define CP_ASYNC16(s, g) \
    asm volatile("cp.async.cg.shared.global [%0], [%1], 16;" :: "r"(s), "l"(g))
#define CP_COMMIT() asm volatile("cp.async.commit_group;")
#define CP_WAIT1()  asm volatile("cp.async.wait_group 1;")

__device__ __forceinline__ void mma8(float* c, const uint32_t* a, const uint32_t* b) {
    asm("mma.sync.aligned.m16n8k8.row.col.f32.tf32.tf32.f32 "
        "{%0,%1,%2,%3}, {%4,%5,%6,%7}, {%8,%9}, {%0,%1,%2,%3};"
        : "+f"(c[0]), "+f"(c[1]), "+f"(c[2]), "+f"(c[3])
        : "r"(a[0]), "r"(a[1]), "r"(a[2]), "r"(a[3]), "r"(b[0]), "r"(b[1]));
}

// ---------------- weight tf32 pre-round ----------------
__global__ __launch_bounds__(256) void cvt_tf32_kernel(const float* __restrict__ src,
                                                       float* __restrict__ dst, int n4) {
    int i = blockIdx.x * 256 + threadIdx.x;
    int stride = gridDim.x * 256;
    for (; i < n4; i += stride) {
        float4 v = ((const float4*)src)[i];
        v.x = tf32r(v.x); v.y = tf32r(v.y); v.z = tf32r(v.z); v.w = tf32r(v.w);
        ((float4*)dst)[i] = v;
    }
}

// ---------------- router ----------------
__global__ __launch_bounds__(256) void router_kernel(const float* __restrict__ x,
                                                     const float* __restrict__ gate_w) {
    __shared__ float gw[NEXP*DIM];
    int t = threadIdx.x;
    for (int i = t; i < NEXP*DIM; i += 256) gw[i] = gate_w[i];
    __syncthreads();
    int warp = t >> 5, lane = t & 31;
    int token = blockIdx.x * 8 + warp;
    const float* xr = x + (size_t)token * DIM;
    float acc[NEXP];
    #pragma unroll
    for (int e = 0; e < NEXP; e++) acc[e] = 0.f;
    #pragma unroll
    for (int i = 0; i < DIM/32; i++) {
        float xv = xr[lane + 32*i];
        #pragma unroll
        for (int e = 0; e < NEXP; e++) acc[e] += xv * gw[e*DIM + lane + 32*i];
    }
    #pragma unroll
    for (int e = 0; e < NEXP; e++) {
        #pragma unroll
        for (int off = 16; off; off >>= 1)
            acc[e] += __shfl_xor_sync(0xffffffffu, acc[e], off);
    }
    if (lane == 0) {
        int i0 = 0;
        #pragma unroll
        for (int e = 1; e < NEXP; e++) if (acc[e] > acc[i0]) i0 = e;
        int i1 = -1;
        #pragma unroll
        for (int e = 0; e < NEXP; e++) {
            if (e == i0) continue;
            if (i1 < 0 || acc[e] > acc[i1]) i1 = e;
        }
        float l0 = acc[i0], l1 = acc[i1];
        g_topk_e[2*token]   = i0;  g_topk_e[2*token+1] = i1;
        g_topk_w[2*token]   = 1.f / (1.f + expf(l1 - l0));
        g_topk_w[2*token+1] = 1.f / (1.f + expf(l0 - l1));
    }
}

// ---------------- dispatch ----------------
__global__ __launch_bounds__(1024) void dispatch_kernel() {
    __shared__ int s[1024][NEXP];
    int tid = threadIdx.x;
    int base_i = tid * 32;
    int cnt[NEXP];
    #pragma unroll
    for (int e = 0; e < NEXP; e++) cnt[e] = 0;
    for (int i = 0; i < 32; i++) cnt[g_topk_e[base_i + i]]++;
    #pragma unroll
    for (int e = 0; e < NEXP; e++) s[tid][e] = cnt[e];
    __syncthreads();
    for (int off = 1; off < 1024; off <<= 1) {
        int v[NEXP];
        if (tid >= off) {
            #pragma unroll
            for (int e = 0; e < NEXP; e++) v[e] = s[tid - off][e];
        }
        __syncthreads();
        if (tid >= off) {
            #pragma unroll
            for (int e = 0; e < NEXP; e++) s[tid][e] += v[e];
        }
        __syncthreads();
    }
    int run[NEXP];
    #pragma unroll
    for (int e = 0; e < NEXP; e++) run[e] = (tid == 0) ? 0 : s[tid-1][e];
    if (tid == 0) {
        for (int e = 0; e < NEXP; e++) {
            int tot = s[1023][e];
            g_count[e] = tot < CAP ? tot : CAP;
        }
    }
    for (int i = 0; i < 32; i++) {
        int idx = base_i + i;
        int e = g_topk_e[idx];
        int pos = run[e]++;
        if (pos < CAP) {
            int slot = e * CAP + pos;
            g_slot_token[slot] = idx >> 1;
            g_assign_slot[idx] = slot;
        } else {
            g_assign_slot[idx] = -1;
        }
    }
}

// ---------------- prep: z = tf32(RMSNorm(2x)*norm_w) ----------------
__global__ __launch_bounds__(256) void prep_kernel(const float* __restrict__ x,
                                                   const float* __restrict__ norm_w) {
    int warp = threadIdx.x >> 5, lane = threadIdx.x & 31;
    int slot = blockIdx.x * 8 + warp;
    int e = slot / CAP, c = slot % CAP;
    if (c >= g_count[e]) return;
    int token = g_slot_token[slot];
    const float* xr = x + (size_t)token * DIM;
    float xv[DIM/32];
    float ss = 0.f;
    #pragma unroll
    for (int i = 0; i < DIM/32; i++) { xv[i] = xr[lane + 32*i]; ss += xv[i]*xv[i]; }
    #pragma unroll
    for (int off = 16; off; off >>= 1) ss += __shfl_xor_sync(0xffffffffu, ss, off);
    float scale = 2.f * rsqrtf(4.f * ss / (float)DIM + 1e-6f);
    float* zr = g_z + (size_t)slot * DIM;
    const float* nw = norm_w + e * DIM;
    #pragma unroll
    for (int i = 0; i < DIM/32; i++)
        zr[lane + 32*i] = tf32r(xv[i] * scale * nw[lane + 32*i]);
}

// ---------------- tf32 mma.sync GEMM kernels ----------------
// Stage layout (floats): A 128 rows x 36, B 128 rows x 36
#define ROWP    36
#define A_F     (128*ROWP)       // 4608
#define STAGE_F (2*A_F)          // 9216
#define NSTAGE  3
#define SMEM_BYTES (NSTAGE*STAGE_F*4)   // 110592

// GEMM1: per expert, 128 slots x 64 h-cols. B rows interleaved: even=gate, odd=up.
__global__ __launch_bounds__(256, 2) void gemm1_tc(const float* __restrict__ w13c) {
    int e = blockIdx.z;
    int m0 = blockIdx.y * 128;
    if (m0 >= g_count[e]) return;
    int n0h = blockIdx.x * 64;

    extern __shared__ float sm[];
    int tid = threadIdx.x;
    const float* Ab = g_z + (size_t)(e * CAP + m0) * DIM;
    const float* Wb = w13c + (size_t)e * 2 * HID * DIM;

    // loader: thread -> 4 float4 for A, 4 float4 for B per stage
    #define G1_ISSUE(stage, chunk) do {                                        \
        float* As_ = sm + (stage) * STAGE_F;                                   \
        float* Bs_ = As_ + A_F;                                                \
        int k0_ = (chunk) * 32;                                                \
        _Pragma("unroll")                                                      \
        for (int j = 0; j < 4; j++) {                                          \
            int fI = tid + 256*j; int row = fI >> 3, c4 = fI & 7;              \
            CP_ASYNC16(smem_u32(As_ + row*ROWP + c4*4),                        \
                       Ab + (size_t)row * DIM + k0_ + c4*4);                   \
        }                                                                      \
        _Pragma("unroll")                                                      \
        for (int j = 0; j < 4; j++) {                                          \
            int fI = tid + 256*j; int r = fI >> 3, c4 = fI & 7;                \
            int gr = (r & 1) ? (HID + n0h + (r >> 1)) : (n0h + (r >> 1));      \
            CP_ASYNC16(smem_u32(Bs_ + r*ROWP + c4*4),                          \
                       Wb + (size_t)gr * DIM + k0_ + c4*4);                    \
        }                                                                      \
    } while (0)

    float c[4][4][4];
    #pragma unroll
    for (int a = 0; a < 4; a++)
        #pragma unroll
        for (int b = 0; b < 4; b++)
            #pragma unroll
            for (int r = 0; r < 4; r++) c[a][b][r] = 0.f;

    int lane = tid & 31, wid = tid >> 5;
    int wr = wid >> 2, wc = wid & 3;
    int qr = lane >> 2, qc = lane & 3;

    G1_ISSUE(0, 0); CP_COMMIT();
    G1_ISSUE(1, 1); CP_COMMIT();

    const int NCH = DIM / 32;   // 24
    for (int i = 0; i < NCH; i++) {
        int s = i % NSTAGE;
        CP_WAIT1();
        __syncthreads();
        if (i + 2 < NCH) G1_ISSUE((i + 2) % NSTAGE, i + 2);
        CP_COMMIT();
        const uint32_t* As = (const uint32_t*)(sm + s * STAGE_F);
        const uint32_t* Bs = As + A_F;
        #pragma unroll
        for (int kk = 0; kk < 4; kk++) {
            uint32_t a[4][4], b[4][2];
            #pragma unroll
            for (int mt = 0; mt < 4; mt++) {
                int base = (wr*64 + mt*16 + qr)*ROWP + kk*8 + qc;
                a[mt][0] = As[base];        a[mt][1] = As[base + 8*ROWP];
                a[mt][2] = As[base + 4];    a[mt][3] = As[base + 8*ROWP + 4];
            }
            #pragma unroll
            for (int nt = 0; nt < 4; nt++) {
                int base = (wc*32 + nt*8 + qr)*ROWP + kk*8 + qc;
                b[nt][0] = Bs[base];        b[nt][1] = Bs[base + 4];
            }
            #pragma unroll
            for (int mt = 0; mt < 4; mt++)
                #pragma unroll
                for (int nt = 0; nt < 4; nt++)
                    mma8(c[mt][nt], a[mt], b[nt]);
        }
    }

    // epilogue: c0=g(r0), c1=u(r0), c2=g(r0+8), c3=u(r0+8); h = silu(g)*u, tf32-rounded
    float* H = g_h + (size_t)(e * CAP + m0) * HID;
    #pragma unroll
    for (int mt = 0; mt < 4; mt++) {
        int r0 = wr*64 + mt*16 + qr;
        #pragma unroll
        for (int nt = 0; nt < 4; nt++) {
            int hcol = n0h + wc*16 + nt*4 + qc;
            float g0 = c[mt][nt][0], u0 = c[mt][nt][1];
            float g1 = c[mt][nt][2], u1 = c[mt][nt][3];
            H[(size_t)r0 * HID + hcol]       = tf32r((g0 / (1.f + expf(-g0))) * u0);
            H[(size_t)(r0 + 8) * HID + hcol] = tf32r((g1 / (1.f + expf(-g1))) * u1);
        }
    }
    #undef G1_ISSUE
}

// GEMM2: per expert, 128 slots x 128 out-dims, K=HID; y = x_token + D
__global__ __launch_bounds__(256, 2) void gemm2_tc(const float* __restrict__ w2c,
                                                   const float* __restrict__ x) {
    int e = blockIdx.z;
    int m0 = blockIdx.y * 128;
    if (m0 >= g_count[e]) return;
    int n0 = blockIdx.x * 128;

    extern __shared__ float sm[];
    int tid = threadIdx.x;
    const float* Ab = g_h + (size_t)(e * CAP + m0) * HID;
    const float* Wb = w2c + (size_t)e * DIM * HID + (size_t)n0 * HID;

    #define G2_ISSUE(stage, chunk) do {                                        \
        float* As_ = sm + (stage) * STAGE_F;                                   \
        float* Bs_ = As_ + A_F;                                                \
        int k0_ = (chunk) * 32;                                                \
        _Pragma("unroll")                                                      \
        for (int j = 0; j < 4; j++) {                                          \
            int fI = tid + 256*j; int row = fI >> 3, c4 = fI & 7;              \
            CP_ASYNC16(smem_u32(As_ + row*ROWP + c4*4),                        \
                       Ab + (size_t)row * HID + k0_ + c4*4);                   \
        }                                                                      \
        _Pragma("unroll")                                                      \
        for (int j = 0; j < 4; j++) {                                          \
            int fI = tid + 256*j; int r = fI >> 3, c4 = fI & 7;                \
            CP_ASYNC16(smem_u32(Bs_ + r*ROWP + c4*4),                          \
                       Wb + (size_t)r * HID + k0_ + c4*4);                     \
        }                                                                      \
    } while (0)

    float c[4][4][4];
    #pragma unroll
    for (int a = 0; a < 4; a++)
        #pragma unroll
        for (int b = 0; b < 4; b++)
            #pragma unroll
            for (int r = 0; r < 4; r++) c[a][b][r] = 0.f;

    int lane = tid & 31, wid = tid >> 5;
    int wr = wid >> 2, wc = wid & 3;
    int qr = lane >> 2, qc = lane & 3;

    G2_ISSUE(0, 0); CP_COMMIT();
    G2_ISSUE(1, 1); CP_COMMIT();

    const int NCH = HID / 32;   // 64
    for (int i = 0; i < NCH; i++) {
        int s = i % NSTAGE;
        CP_WAIT1();
        __syncthreads();
        if (i + 2 < NCH) G2_ISSUE((i + 2) % NSTAGE, i + 2);
        CP_COMMIT();
        const uint32_t* As = (const uint32_t*)(sm + s * STAGE_F);
        const uint32_t* Bs = As + A_F;
        #pragma unroll
        for (int kk = 0; kk < 4; kk++) {
            uint32_t a[4][4], b[4][2];
            #pragma unroll
            for (int mt = 0; mt < 4; mt++) {
                int base = (wr*64 + mt*16 + qr)*ROWP + kk*8 + qc;
                a[mt][0] = As[base];        a[mt][1] = As[base + 8*ROWP];
                a[mt][2] = As[base + 4];    a[mt][3] = As[base + 8*ROWP + 4];
            }
            #pragma unroll
            for (int nt = 0; nt < 4; nt++) {
                int base = (wc*32 + nt*8 + qr)*ROWP + kk*8 + qc;
                b[nt][0] = Bs[base];        b[nt][1] = Bs[base + 4];
            }
            #pragma unroll
            for (int mt = 0; mt < 4; mt++)
                #pragma unroll
                for (int nt = 0; nt < 4; nt++)
                    mma8(c[mt][nt], a[mt], b[nt]);
        }
    }

    // epilogue: y = x[token] + D
    #pragma unroll
    for (int mt = 0; mt < 4; mt++) {
        int r0 = wr*64 + mt*16 + qr;
        int slot0 = e * CAP + m0 + r0;
        int slot1 = slot0 + 8;
        int t0 = g_slot_token[slot0];
        int t1 = g_slot_token[slot1];
        #pragma unroll
        for (int nt = 0; nt < 4; nt++) {
            int col = n0 + wc*32 + nt*8 + qc*2;
            float2 x0 = *(const float2*)&x[(size_t)t0 * DIM + col];
            float2 x1 = *(const float2*)&x[(size_t)t1 * DIM + col];
            float2 y0, y1;
            y0.x = x0.x + c[mt][nt][0];  y0.y = x0.y + c[mt][nt][1];
            y1.x = x1.x + c[mt][nt][2];  y1.y = x1.y + c[mt][nt][3];
            *(float2*)&g_y[(size_t)slot0 * DIM + col] = y0;
            *(float2*)&g_y[(size_t)slot1 * DIM + col] = y1;
        }
    }
    #undef G2_ISSUE
}

// ---------------- combine ----------------
__global__ __launch_bounds__(256) void combine_kernel(float* __restrict__ out) {
    int idx = blockIdx.x * 256 + threadIdx.x;
    if (idx >= N_TOK * DIM) return;
    int n = idx / DIM, d = idx - n * DIM;
    float r = 0.f;
    int s0 = g_assign_slot[2*n], s1 = g_assign_slot[2*n + 1];
    if (s0 >= 0) r += g_topk_w[2*n]     * g_y[(size_t)s0 * DIM + d];
    if (s1 >= 0) r += g_topk_w[2*n + 1] * g_y[(size_t)s1 * DIM + d];
    out[idx] = r;
}

// ---------------- launch ----------------
extern "C" void kernel_launch(void* const* d_in, const int* in_sizes, int n_in,
                              void* d_out, int out_size) {
    const float* x      = (const float*)d_in[0];
    const float* gate_w = (const float*)d_in[1];
    const float* w13    = (const float*)d_in[2];
    const float* w2     = (const float*)d_in[3];
    const float* norm_w = (const float*)d_in[4];
    float* out = (float*)d_out;

    cudaFuncSetAttribute(gemm1_tc, cudaFuncAttributeMaxDynamicSharedMemorySize, SMEM_BYTES);
    cudaFuncSetAttribute(gemm2_tc, cudaFuncAttributeMaxDynamicSharedMemorySize, SMEM_BYTES);

    float* w13c; cudaGetSymbolAddress((void**)&w13c, g_w13c);
    float* w2c;  cudaGetSymbolAddress((void**)&w2c,  g_w2c);

    cvt_tf32_kernel<<<4096, 256>>>(w13, w13c, W13N/4);
    cvt_tf32_kernel<<<4096, 256>>>(w2,  w2c,  W2N/4);
    router_kernel  <<<N_TOK/8, 256>>>(x, gate_w);
    dispatch_kernel<<<1, 1024>>>();
    prep_kernel    <<<NSLOT/8, 256>>>(x, norm_w);
    gemm1_tc       <<<dim3(HID/64, CAP/128, NEXP), 256, SMEM_BYTES>>>(w13c);
    gemm2_tc       <<<dim3(DIM/128, CAP/128, NEXP), 256, SMEM_BYTES>>>(w2c, x);
    combine_kernel <<<(N_TOK*DIM + 255)/256, 256>>>(out);
}

// round 5
// speedup vs baseline: 7.0457x; 1.7274x over previous
#include <cuda_runtime.h>
#include <cuda_fp16.h>
#include <math.h>
#include <stdint.h>

// Problem constants
#define N_TOK 16384
#define DIM   768
#define NEXP  8
#define HID   2048
#define CAP   5120
#define NK    (N_TOK*2)
#define NSLOT (NEXP*CAP)

#define W13N (NEXP*2*HID*DIM)
#define W2N  (NEXP*DIM*HID)

// ---------------- device scratch ----------------
__device__ int    g_topk_e[NK];
__device__ float  g_topk_w[NK];
__device__ int    g_assign_slot[NK];
__device__ int    g_count[NEXP];
__device__ int    g_slot_token[NSLOT];
__device__ __half g_z[(size_t)NSLOT*DIM];
__device__ __half g_h[(size_t)NSLOT*HID];
__device__ float  g_y[(size_t)NSLOT*DIM];
__device__ __half g_w13h[W13N];
__device__ __half g_w2h[W2N];

// ---------------- helpers ----------------
__device__ __forceinline__ uint32_t smem_u32(const void* p) {
    uint32_t a;
    asm("{ .reg .u64 t; cvta.to.shared.u64 t, %1; cvt.u32.u64 %0, t; }" : "=r"(a) : "l"(p));
    return a;
}
#define CP_ASYNC16(s, g) \
    asm volatile("cp.async.cg.shared.global [%0], [%1], 16;" :: "r"(s), "l"(g))
#define CP_COMMIT() asm volatile("cp.async.commit_group;")
#define CP_WAIT1()  asm volatile("cp.async.wait_group 1;")

__device__ __forceinline__ void mma16(float* c, const uint32_t* a, const uint32_t* b) {
    asm("mma.sync.aligned.m16n8k16.row.col.f32.f16.f16.f32 "
        "{%0,%1,%2,%3}, {%4,%5,%6,%7}, {%8,%9}, {%0,%1,%2,%3};"
        : "+f"(c[0]), "+f"(c[1]), "+f"(c[2]), "+f"(c[3])
        : "r"(a[0]), "r"(a[1]), "r"(a[2]), "r"(a[3]), "r"(b[0]), "r"(b[1]));
}

// ---------------- weight f32 -> f16 ----------------
__global__ __launch_bounds__(256) void cvt_half_kernel(const float* __restrict__ src,
                                                       __half* __restrict__ dst, int n4) {
    int i = blockIdx.x * 256 + threadIdx.x;
    int stride = gridDim.x * 256;
    for (; i < n4; i += stride) {
        float4 v = ((const float4*)src)[i];
        __half2 h0 = __floats2half2_rn(v.x, v.y);
        __half2 h1 = __floats2half2_rn(v.z, v.w);
        uint2 pk;
        pk.x = *(uint32_t*)&h0;  pk.y = *(uint32_t*)&h1;
        ((uint2*)dst)[i] = pk;
    }
}

// ---------------- router ----------------
__global__ __launch_bounds__(256) void router_kernel(const float* __restrict__ x,
                                                     const float* __restrict__ gate_w) {
    __shared__ float gw[NEXP*DIM];
    int t = threadIdx.x;
    for (int i = t; i < NEXP*DIM; i += 256) gw[i] = gate_w[i];
    __syncthreads();
    int warp = t >> 5, lane = t & 31;
    int token = blockIdx.x * 8 + warp;
    const float* xr = x + (size_t)token * DIM;
    float acc[NEXP];
    #pragma unroll
    for (int e = 0; e < NEXP; e++) acc[e] = 0.f;
    #pragma unroll
    for (int i = 0; i < DIM/32; i++) {
        float xv = xr[lane + 32*i];
        #pragma unroll
        for (int e = 0; e < NEXP; e++) acc[e] += xv * gw[e*DIM + lane + 32*i];
    }
    #pragma unroll
    for (int e = 0; e < NEXP; e++) {
        #pragma unroll
        for (int off = 16; off; off >>= 1)
            acc[e] += __shfl_xor_sync(0xffffffffu, acc[e], off);
    }
    if (lane == 0) {
        int i0 = 0;
        #pragma unroll
        for (int e = 1; e < NEXP; e++) if (acc[e] > acc[i0]) i0 = e;
        int i1 = -1;
        #pragma unroll
        for (int e = 0; e < NEXP; e++) {
            if (e == i0) continue;
            if (i1 < 0 || acc[e] > acc[i1]) i1 = e;
        }
        float l0 = acc[i0], l1 = acc[i1];
        g_topk_e[2*token]   = i0;  g_topk_e[2*token+1] = i1;
        g_topk_w[2*token]   = 1.f / (1.f + expf(l1 - l0));
        g_topk_w[2*token+1] = 1.f / (1.f + expf(l0 - l1));
    }
}

// ---------------- dispatch: register-resident counting ----------------
__global__ __launch_bounds__(1024) void dispatch_kernel() {
    __shared__ int s[1024][NEXP];
    int tid = threadIdx.x;
    int base_i = tid * 32;

    int ev[32];
    const int4* tp = (const int4*)(g_topk_e + base_i);
    #pragma unroll
    for (int q = 0; q < 8; q++) {
        int4 v = tp[q];
        ev[4*q+0] = v.x; ev[4*q+1] = v.y; ev[4*q+2] = v.z; ev[4*q+3] = v.w;
    }
    int cnt[NEXP];
    #pragma unroll
    for (int e = 0; e < NEXP; e++) cnt[e] = 0;
    #pragma unroll
    for (int i = 0; i < 32; i++) {
        #pragma unroll
        for (int e = 0; e < NEXP; e++) cnt[e] += (ev[i] == e);
    }
    #pragma unroll
    for (int e = 0; e < NEXP; e++) s[tid][e] = cnt[e];
    __syncthreads();
    for (int off = 1; off < 1024; off <<= 1) {
        int v[NEXP];
        if (tid >= off) {
            #pragma unroll
            for (int e = 0; e < NEXP; e++) v[e] = s[tid - off][e];
        }
        __syncthreads();
        if (tid >= off) {
            #pragma unroll
            for (int e = 0; e < NEXP; e++) s[tid][e] += v[e];
        }
        __syncthreads();
    }
    int run[NEXP];
    #pragma unroll
    for (int e = 0; e < NEXP; e++) run[e] = (tid == 0) ? 0 : s[tid-1][e];
    if (tid == 0) {
        #pragma unroll
        for (int e = 0; e < NEXP; e++) {
            int tot = s[1023][e];
            g_count[e] = tot < CAP ? tot : CAP;
        }
    }
    #pragma unroll
    for (int i = 0; i < 32; i++) {
        int idx = base_i + i;
        int eV = ev[i];
        int pos = 0;
        #pragma unroll
        for (int e = 0; e < NEXP; e++) if (eV == e) pos = run[e]++;
        if (pos < CAP) {
            int slot = eV * CAP + pos;
            g_slot_token[slot] = idx >> 1;
            g_assign_slot[idx] = slot;
        } else {
            g_assign_slot[idx] = -1;
        }
    }
}

// ---------------- prep: z = half(RMSNorm(2x)*norm_w) ----------------
__global__ __launch_bounds__(256) void prep_kernel(const float* __restrict__ x,
                                                   const float* __restrict__ norm_w) {
    int warp = threadIdx.x >> 5, lane = threadIdx.x & 31;
    int slot = blockIdx.x * 8 + warp;
    int e = slot / CAP, c = slot % CAP;
    if (c >= g_count[e]) return;
    int token = g_slot_token[slot];
    const float* xr = x + (size_t)token * DIM;
    float xv[DIM/32];
    float ss = 0.f;
    #pragma unroll
    for (int i = 0; i < DIM/32; i++) { xv[i] = xr[lane + 32*i]; ss += xv[i]*xv[i]; }
    #pragma unroll
    for (int off = 16; off; off >>= 1) ss += __shfl_xor_sync(0xffffffffu, ss, off);
    float scale = 2.f * rsqrtf(4.f * ss / (float)DIM + 1e-6f);
    __half* zr = g_z + (size_t)slot * DIM;
    const float* nw = norm_w + e * DIM;
    #pragma unroll
    for (int i = 0; i < DIM/32; i++)
        zr[lane + 32*i] = __float2half_rn(xv[i] * scale * nw[lane + 32*i]);
}

// ---------------- fp16 mma.sync GEMM kernels ----------------
// Chunk = 64 halves of K (128B per row). Row pitch = 72 halves (36 u32).
#define ROWP32  36
#define A_U32   (128*ROWP32)       // per-matrix u32 per stage
#define STAGE_U32 (2*A_U32)
#define NSTAGE  3
#define SMEM_BYTES (NSTAGE*STAGE_U32*4)   // 110592

// GEMM1: per expert, 128 slots x 64 h-cols; B rows interleaved even=gate, odd=up; K=DIM
__global__ __launch_bounds__(256, 2) void gemm1_tc(const __half* __restrict__ w13h) {
    int e = blockIdx.z;
    int m0 = blockIdx.y * 128;
    if (m0 >= g_count[e]) return;
    int n0h = blockIdx.x * 64;

    extern __shared__ uint32_t sm[];
    int tid = threadIdx.x;
    const __half* Ab = g_z + (size_t)(e * CAP + m0) * DIM;
    const __half* Wb = w13h + (size_t)e * 2 * HID * DIM;

    #define G1_ISSUE(stage, chunk) do {                                        \
        uint32_t* As_ = sm + (stage) * STAGE_U32;                              \
        uint32_t* Bs_ = As_ + A_U32;                                           \
        int k0_ = (chunk) * 64;                                                \
        _Pragma("unroll")                                                      \
        for (int j = 0; j < 4; j++) {                                          \
            int fI = tid + 256*j; int row = fI >> 3, c8 = fI & 7;              \
            CP_ASYNC16(smem_u32(As_ + row*ROWP32 + c8*4),                      \
                       Ab + (size_t)row * DIM + k0_ + c8*8);                   \
        }                                                                      \
        _Pragma("unroll")                                                      \
        for (int j = 0; j < 4; j++) {                                          \
            int fI = tid + 256*j; int r = fI >> 3, c8 = fI & 7;                \
            int gr = (r & 1) ? (HID + n0h + (r >> 1)) : (n0h + (r >> 1));      \
            CP_ASYNC16(smem_u32(Bs_ + r*ROWP32 + c8*4),                        \
                       Wb + (size_t)gr * DIM + k0_ + c8*8);                    \
        }                                                                      \
    } while (0)

    float c[4][4][4];
    #pragma unroll
    for (int a = 0; a < 4; a++)
        #pragma unroll
        for (int b = 0; b < 4; b++)
            #pragma unroll
            for (int r = 0; r < 4; r++) c[a][b][r] = 0.f;

    int lane = tid & 31, wid = tid >> 5;
    int wr = wid >> 2, wc = wid & 3;
    int qr = lane >> 2, qc = lane & 3;

    G1_ISSUE(0, 0); CP_COMMIT();
    G1_ISSUE(1, 1); CP_COMMIT();

    const int NCH = DIM / 64;   // 12
    for (int i = 0; i < NCH; i++) {
        int s = i % NSTAGE;
        CP_WAIT1();
        __syncthreads();
        if (i + 2 < NCH) G1_ISSUE((i + 2) % NSTAGE, i + 2);
        CP_COMMIT();
        const uint32_t* As = sm + s * STAGE_U32;
        const uint32_t* Bs = As + A_U32;
        #pragma unroll
        for (int kk = 0; kk < 4; kk++) {   // 4 x k16 steps
            uint32_t a[4][4], b[4][2];
            #pragma unroll
            for (int mt = 0; mt < 4; mt++) {
                int base = (wr*64 + mt*16 + qr)*ROWP32 + kk*8 + qc;
                a[mt][0] = As[base];        a[mt][1] = As[base + 8*ROWP32];
                a[mt][2] = As[base + 4];    a[mt][3] = As[base + 8*ROWP32 + 4];
            }
            #pragma unroll
            for (int nt = 0; nt < 4; nt++) {
                int base = (wc*32 + nt*8 + qr)*ROWP32 + kk*8 + qc;
                b[nt][0] = Bs[base];        b[nt][1] = Bs[base + 4];
            }
            #pragma unroll
            for (int mt = 0; mt < 4; mt++)
                #pragma unroll
                for (int nt = 0; nt < 4; nt++)
                    mma16(c[mt][nt], a[mt], b[nt]);
        }
    }

    // epilogue: c0=g(r0), c1=u(r0), c2=g(r0+8), c3=u(r0+8) -> h = silu(g)*u (half)
    __half* H = g_h + (size_t)(e * CAP + m0) * HID;
    #pragma unroll
    for (int mt = 0; mt < 4; mt++) {
        int r0 = wr*64 + mt*16 + qr;
        #pragma unroll
        for (int nt = 0; nt < 4; nt++) {
            int hcol = n0h + wc*16 + nt*4 + qc;
            float g0 = c[mt][nt][0], u0 = c[mt][nt][1];
            float g1 = c[mt][nt][2], u1 = c[mt][nt][3];
            H[(size_t)r0 * HID + hcol]       = __float2half_rn((g0 / (1.f + expf(-g0))) * u0);
            H[(size_t)(r0 + 8) * HID + hcol] = __float2half_rn((g1 / (1.f + expf(-g1))) * u1);
        }
    }
    #undef G1_ISSUE
}

// GEMM2: per expert, 128 slots x 128 out-dims, K=HID; y = x_token + D
__global__ __launch_bounds__(256, 2) void gemm2_tc(const __half* __restrict__ w2h,
                                                   const float* __restrict__ x) {
    int e = blockIdx.z;
    int m0 = blockIdx.y * 128;
    if (m0 >= g_count[e]) return;
    int n0 = blockIdx.x * 128;

    extern __shared__ uint32_t sm[];
    int tid = threadIdx.x;
    const __half* Ab = g_h + (size_t)(e * CAP + m0) * HID;
    const __half* Wb = w2h + (size_t)e * DIM * HID + (size_t)n0 * HID;

    #define G2_ISSUE(stage, chunk) do {                                        \
        uint32_t* As_ = sm + (stage) * STAGE_U32;                              \
        uint32_t* Bs_ = As_ + A_U32;                                           \
        int k0_ = (chunk) * 64;                                                \
        _Pragma("unroll")                                                      \
        for (int j = 0; j < 4; j++) {                                          \
            int fI = tid + 256*j; int row = fI >> 3, c8 = fI & 7;              \
            CP_ASYNC16(smem_u32(As_ + row*ROWP32 + c8*4),                      \
                       Ab + (size_t)row * HID + k0_ + c8*8);                   \
        }                                                                      \
        _Pragma("unroll")                                                      \
        for (int j = 0; j < 4; j++) {                                          \
            int fI = tid + 256*j; int r = fI >> 3, c8 = fI & 7;                \
            CP_ASYNC16(smem_u32(Bs_ + r*ROWP32 + c8*4),                        \
                       Wb + (size_t)r * HID + k0_ + c8*8);                     \
        }                                                                      \
    } while (0)

    float c[4][4][4];
    #pragma unroll
    for (int a = 0; a < 4; a++)
        #pragma unroll
        for (int b = 0; b < 4; b++)
            #pragma unroll
            for (int r = 0; r < 4; r++) c[a][b][r] = 0.f;

    int lane = tid & 31, wid = tid >> 5;
    int wr = wid >> 2, wc = wid & 3;
    int qr = lane >> 2, qc = lane & 3;

    G2_ISSUE(0, 0); CP_COMMIT();
    G2_ISSUE(1, 1); CP_COMMIT();

    const int NCH = HID / 64;   // 32
    for (int i = 0; i < NCH; i++) {
        int s = i % NSTAGE;
        CP_WAIT1();
        __syncthreads();
        if (i + 2 < NCH) G2_ISSUE((i + 2) % NSTAGE, i + 2);
        CP_COMMIT();
        const uint32_t* As = sm + s * STAGE_U32;
        const uint32_t* Bs = As + A_U32;
        #pragma unroll
        for (int kk = 0; kk < 4; kk++) {
            uint32_t a[4][4], b[4][2];
            #pragma unroll
            for (int mt = 0; mt < 4; mt++) {
                int base = (wr*64 + mt*16 + qr)*ROWP32 + kk*8 + qc;
                a[mt][0] = As[base];        a[mt][1] = As[base + 8*ROWP32];
                a[mt][2] = As[base + 4];    a[mt][3] = As[base + 8*ROWP32 + 4];
            }
            #pragma unroll
            for (int nt = 0; nt < 4; nt++) {
                int base = (wc*32 + nt*8 + qr)*ROWP32 + kk*8 + qc;
                b[nt][0] = Bs[base];        b[nt][1] = Bs[base + 4];
            }
            #pragma unroll
            for (int mt = 0; mt < 4; mt++)
                #pragma unroll
                for (int nt = 0; nt < 4; nt++)
                    mma16(c[mt][nt], a[mt], b[nt]);
        }
    }

    #pragma unroll
    for (int mt = 0; mt < 4; mt++) {
        int r0 = wr*64 + mt*16 + qr;
        int slot0 = e * CAP + m0 + r0;
        int slot1 = slot0 + 8;
        int t0 = g_slot_token[slot0];
        int t1 = g_slot_token[slot1];
        #pragma unroll
        for (int nt = 0; nt < 4; nt++) {
            int col = n0 + wc*32 + nt*8 + qc*2;
            float2 x0 = *(const float2*)&x[(size_t)t0 * DIM + col];
            float2 x1 = *(const float2*)&x[(size_t)t1 * DIM + col];
            float2 y0, y1;
            y0.x = x0.x + c[mt][nt][0];  y0.y = x0.y + c[mt][nt][1];
            y1.x = x1.x + c[mt][nt][2];  y1.y = x1.y + c[mt][nt][3];
            *(float2*)&g_y[(size_t)slot0 * DIM + col] = y0;
            *(float2*)&g_y[(size_t)slot1 * DIM + col] = y1;
        }
    }
    #undef G2_ISSUE
}

// ---------------- combine ----------------
__global__ __launch_bounds__(256) void combine_kernel(float* __restrict__ out) {
    int idx = blockIdx.x * 256 + threadIdx.x;
    if (idx >= N_TOK * DIM) return;
    int n = idx / DIM, d = idx - n * DIM;
    float r = 0.f;
    int s0 = g_assign_slot[2*n], s1 = g_assign_slot[2*n + 1];
    if (s0 >= 0) r += g_topk_w[2*n]     * g_y[(size_t)s0 * DIM + d];
    if (s1 >= 0) r += g_topk_w[2*n + 1] * g_y[(size_t)s1 * DIM + d];
    out[idx] = r;
}

// ---------------- launch ----------------
extern "C" void kernel_launch(void* const* d_in, const int* in_sizes, int n_in,
                              void* d_out, int out_size) {
    const float* x      = (const float*)d_in[0];
    const float* gate_w = (const float*)d_in[1];
    const float* w13    = (const float*)d_in[2];
    const float* w2     = (const float*)d_in[3];
    const float* norm_w = (const float*)d_in[4];
    float* out = (float*)d_out;

    cudaFuncSetAttribute(gemm1_tc, cudaFuncAttributeMaxDynamicSharedMemorySize, SMEM_BYTES);
    cudaFuncSetAttribute(gemm2_tc, cudaFuncAttributeMaxDynamicSharedMemorySize, SMEM_BYTES);

    __half* w13h; cudaGetSymbolAddress((void**)&w13h, g_w13h);
    __half* w2h;  cudaGetSymbolAddress((void**)&w2h,  g_w2h);

    cvt_half_kernel<<<4096, 256>>>(w13, w13h, W13N/4);
    cvt_half_kernel<<<4096, 256>>>(w2,  w2h,  W2N/4);
    router_kernel  <<<N_TOK/8, 256>>>(x, gate_w);
    dispatch_kernel<<<1, 1024>>>();
    prep_kernel    <<<NSLOT/8, 256>>>(x, norm_w);
    gemm1_tc       <<<dim3(HID/64, CAP/128, NEXP), 256, SMEM_BYTES>>>(w13h);
    gemm2_tc       <<<dim3(DIM/128, CAP/128, NEXP), 256, SMEM_BYTES>>>(w2h, x);
    combine_kernel <<<(N_TOK*DIM + 255)/256, 256>>>(out);
}

// round 6
// speedup vs baseline: 7.6763x; 1.0895x over previous
#include <cuda_runtime.h>
#include <cuda_fp16.h>
#include <math.h>
#include <stdint.h>

// Problem constants
#define N_TOK 16384
#define DIM   768
#define NEXP  8
#define HID   2048
#define CAP   5120
#define NK    (N_TOK*2)
#define NSLOT (NEXP*CAP)
#define NSEG  64
#define SEGSZ (NK/NSEG)     // 512 assignments per segment

#define W13N (NEXP*2*HID*DIM)
#define W2N  (NEXP*DIM*HID)

// ---------------- device scratch ----------------
__device__ int    g_topk_e[NK];
__device__ float  g_topk_w[NK];
__device__ int    g_assign_slot[NK];
__device__ int    g_count[NEXP];
__device__ int    g_slot_token[NSLOT];
__device__ int    g_seg_hist[NSEG][NEXP];
__device__ int    g_seg_base[NSEG][NEXP];
__device__ __half g_z[(size_t)NSLOT*DIM];
__device__ __half g_h[(size_t)NSLOT*HID];
__device__ float  g_y[(size_t)NSLOT*DIM];
__device__ __half g_w13h[W13N];
__device__ __half g_w2h[W2N];

// ---------------- helpers ----------------
__device__ __forceinline__ uint32_t smem_u32(const void* p) {
    uint32_t a;
    asm("{ .reg .u64 t; cvta.to.shared.u64 t, %1; cvt.u32.u64 %0, t; }" : "=r"(a) : "l"(p));
    return a;
}
#define CP_ASYNC16(s, g) \
    asm volatile("cp.async.cg.shared.global [%0], [%1], 16;" :: "r"(s), "l"(g))
#define CP_COMMIT() asm volatile("cp.async.commit_group;")
#define CP_WAIT1()  asm volatile("cp.async.wait_group 1;")

__device__ __forceinline__ void mma16(float* c, const uint32_t* a, const uint32_t* b) {
    asm("mma.sync.aligned.m16n8k16.row.col.f32.f16.f16.f32 "
        "{%0,%1,%2,%3}, {%4,%5,%6,%7}, {%8,%9}, {%0,%1,%2,%3};"
        : "+f"(c[0]), "+f"(c[1]), "+f"(c[2]), "+f"(c[3])
        : "r"(a[0]), "r"(a[1]), "r"(a[2]), "r"(a[3]), "r"(b[0]), "r"(b[1]));
}

// ---------------- weight f32 -> f16 ----------------
__global__ __launch_bounds__(256) void cvt_half_kernel(const float* __restrict__ src,
                                                       __half* __restrict__ dst, int n4) {
    int i = blockIdx.x * 256 + threadIdx.x;
    int stride = gridDim.x * 256;
    for (; i < n4; i += stride) {
        float4 v = ((const float4*)src)[i];
        __half2 h0 = __floats2half2_rn(v.x, v.y);
        __half2 h1 = __floats2half2_rn(v.z, v.w);
        uint2 pk;
        pk.x = *(uint32_t*)&h0;  pk.y = *(uint32_t*)&h1;
        ((uint2*)dst)[i] = pk;
    }
}

// ---------------- router ----------------
__global__ __launch_bounds__(256) void router_kernel(const float* __restrict__ x,
                                                     const float* __restrict__ gate_w) {
    __shared__ float gw[NEXP*DIM];
    int t = threadIdx.x;
    for (int i = t; i < NEXP*DIM; i += 256) gw[i] = gate_w[i];
    __syncthreads();
    int warp = t >> 5, lane = t & 31;
    int token = blockIdx.x * 8 + warp;
    const float* xr = x + (size_t)token * DIM;
    float acc[NEXP];
    #pragma unroll
    for (int e = 0; e < NEXP; e++) acc[e] = 0.f;
    #pragma unroll
    for (int i = 0; i < DIM/32; i++) {
        float xv = xr[lane + 32*i];
        #pragma unroll
        for (int e = 0; e < NEXP; e++) acc[e] += xv * gw[e*DIM + lane + 32*i];
    }
    #pragma unroll
    for (int e = 0; e < NEXP; e++) {
        #pragma unroll
        for (int off = 16; off; off >>= 1)
            acc[e] += __shfl_xor_sync(0xffffffffu, acc[e], off);
    }
    if (lane == 0) {
        int i0 = 0;
        #pragma unroll
        for (int e = 1; e < NEXP; e++) if (acc[e] > acc[i0]) i0 = e;
        int i1 = -1;
        #pragma unroll
        for (int e = 0; e < NEXP; e++) {
            if (e == i0) continue;
            if (i1 < 0 || acc[e] > acc[i1]) i1 = e;
        }
        float l0 = acc[i0], l1 = acc[i1];
        g_topk_e[2*token]   = i0;  g_topk_e[2*token+1] = i1;
        g_topk_w[2*token]   = 1.f / (1.f + expf(l1 - l0));
        g_topk_w[2*token+1] = 1.f / (1.f + expf(l0 - l1));
    }
}

// ---------------- dispatch phase 1: per-segment histogram ----------------
__global__ __launch_bounds__(256) void disp_count_kernel() {
    __shared__ int h[NEXP];
    int t = threadIdx.x, b = blockIdx.x;
    if (t < NEXP) h[t] = 0;
    __syncthreads();
    int2 ev = *(const int2*)(g_topk_e + b * SEGSZ + 2 * t);
    atomicAdd(&h[ev.x], 1);
    atomicAdd(&h[ev.y], 1);
    __syncthreads();
    if (t < NEXP) g_seg_hist[b][t] = h[t];
}

// ---------------- dispatch phase 2: scan segments per expert ----------------
__global__ __launch_bounds__(32) void disp_scan_kernel() {
    int e = threadIdx.x;
    if (e >= NEXP) return;
    int run = 0;
    for (int s = 0; s < NSEG; s++) {
        g_seg_base[s][e] = run;
        run += g_seg_hist[s][e];
    }
    g_count[e] = run < CAP ? run : CAP;
}

// ---------------- dispatch phase 3: exact serial-order ranks ----------------
__global__ __launch_bounds__(256) void disp_assign_kernel() {
    __shared__ int s[256][NEXP];
    int t = threadIdx.x, b = blockIdx.x;
    int idx0 = b * SEGSZ + 2 * t;
    int2 ev = *(const int2*)(g_topk_e + idx0);

    int cnt[NEXP];
    #pragma unroll
    for (int e = 0; e < NEXP; e++) cnt[e] = (ev.x == e) + (ev.y == e);
    #pragma unroll
    for (int e = 0; e < NEXP; e++) s[t][e] = cnt[e];
    __syncthreads();
    for (int off = 1; off < 256; off <<= 1) {
        int v[NEXP];
        if (t >= off) {
            #pragma unroll
            for (int e = 0; e < NEXP; e++) v[e] = s[t - off][e];
        }
        __syncthreads();
        if (t >= off) {
            #pragma unroll
            for (int e = 0; e < NEXP; e++) s[t][e] += v[e];
        }
        __syncthreads();
    }
    // exclusive prefix within segment + segment base
    int pos0 = 0, pos1 = 0;
    #pragma unroll
    for (int e = 0; e < NEXP; e++) {
        int pref = (t == 0 ? 0 : s[t-1][e]) + g_seg_base[b][e];
        if (ev.x == e) pos0 = pref;
        if (ev.y == e) pos1 = pref + (ev.x == e);
    }
    if (pos0 < CAP) {
        int slot = ev.x * CAP + pos0;
        g_slot_token[slot] = idx0 >> 1;
        g_assign_slot[idx0] = slot;
    } else g_assign_slot[idx0] = -1;
    if (pos1 < CAP) {
        int slot = ev.y * CAP + pos1;
        g_slot_token[slot] = (idx0 + 1) >> 1;
        g_assign_slot[idx0 + 1] = slot;
    } else g_assign_slot[idx0 + 1] = -1;
}

// ---------------- prep: z = half(RMSNorm(2x)*norm_w) ----------------
__global__ __launch_bounds__(256) void prep_kernel(const float* __restrict__ x,
                                                   const float* __restrict__ norm_w) {
    int warp = threadIdx.x >> 5, lane = threadIdx.x & 31;
    int slot = blockIdx.x * 8 + warp;
    int e = slot / CAP, c = slot % CAP;
    if (c >= g_count[e]) return;
    int token = g_slot_token[slot];
    const float* xr = x + (size_t)token * DIM;
    float xv[DIM/32];
    float ss = 0.f;
    #pragma unroll
    for (int i = 0; i < DIM/32; i++) { xv[i] = xr[lane + 32*i]; ss += xv[i]*xv[i]; }
    #pragma unroll
    for (int off = 16; off; off >>= 1) ss += __shfl_xor_sync(0xffffffffu, ss, off);
    float scale = 2.f * rsqrtf(4.f * ss / (float)DIM + 1e-6f);
    __half* zr = g_z + (size_t)slot * DIM;
    const float* nw = norm_w + e * DIM;
    #pragma unroll
    for (int i = 0; i < DIM/32; i++)
        zr[lane + 32*i] = __float2half_rn(xv[i] * scale * nw[lane + 32*i]);
}

// ---------------- fp16 mma.sync GEMMs: CTA 128x128, 4 warps (2x2 of 64x64) ----------
#define ROWP32  36
#define A_U32   (128*ROWP32)
#define STAGE_U32 (2*A_U32)
#define NSTAGE  3
#define SMEM_BYTES (NSTAGE*STAGE_U32*4)   // 110592

// GEMM1: 128 slots x 128 gu-cols (=64 h-cols), B rows even=gate odd=up, K=DIM
__global__ __launch_bounds__(128, 2) void gemm1_tc(const __half* __restrict__ w13h) {
    int e = blockIdx.z;
    int m0 = blockIdx.y * 128;
    if (m0 >= g_count[e]) return;
    int n0h = blockIdx.x * 64;

    extern __shared__ uint32_t sm[];
    int tid = threadIdx.x;
    const __half* Ab = g_z + (size_t)(e * CAP + m0) * DIM;
    const __half* Wb = w13h + (size_t)e * 2 * HID * DIM;

    // loader: 128 threads, 8 lines of 16B each per matrix per stage
    #define G1_ISSUE(stage, chunk) do {                                        \
        uint32_t* As_ = sm + (stage) * STAGE_U32;                              \
        uint32_t* Bs_ = As_ + A_U32;                                           \
        int k0_ = (chunk) * 64;                                                \
        _Pragma("unroll")                                                      \
        for (int j = 0; j < 8; j++) {                                          \
            int fI = tid + 128*j; int row = fI >> 3, c8 = fI & 7;              \
            CP_ASYNC16(smem_u32(As_ + row*ROWP32 + c8*4),                      \
                       Ab + (size_t)row * DIM + k0_ + c8*8);                   \
        }                                                                      \
        _Pragma("unroll")                                                      \
        for (int j = 0; j < 8; j++) {                                          \
            int fI = tid + 128*j; int r = fI >> 3, c8 = fI & 7;                \
            int gr = (r & 1) ? (HID + n0h + (r >> 1)) : (n0h + (r >> 1));      \
            CP_ASYNC16(smem_u32(Bs_ + r*ROWP32 + c8*4),                        \
                       Wb + (size_t)gr * DIM + k0_ + c8*8);                    \
        }                                                                      \
    } while (0)

    float c[4][8][4];
    #pragma unroll
    for (int a = 0; a < 4; a++)
        #pragma unroll
        for (int b = 0; b < 8; b++)
            #pragma unroll
            for (int r = 0; r < 4; r++) c[a][b][r] = 0.f;

    int lane = tid & 31, wid = tid >> 5;
    int wr = wid >> 1, wc = wid & 1;
    int qr = lane >> 2, qc = lane & 3;

    G1_ISSUE(0, 0); CP_COMMIT();
    G1_ISSUE(1, 1); CP_COMMIT();

    const int NCH = DIM / 64;   // 12
    for (int i = 0; i < NCH; i++) {
        int s = i % NSTAGE;
        CP_WAIT1();
        __syncthreads();
        if (i + 2 < NCH) G1_ISSUE((i + 2) % NSTAGE, i + 2);
        CP_COMMIT();
        const uint32_t* As = sm + s * STAGE_U32;
        const uint32_t* Bs = As + A_U32;
        #pragma unroll
        for (int kk = 0; kk < 4; kk++) {
            uint32_t a[4][4], b[8][2];
            #pragma unroll
            for (int mt = 0; mt < 4; mt++) {
                int base = (wr*64 + mt*16 + qr)*ROWP32 + kk*8 + qc;
                a[mt][0] = As[base];        a[mt][1] = As[base + 8*ROWP32];
                a[mt][2] = As[base + 4];    a[mt][3] = As[base + 8*ROWP32 + 4];
            }
            #pragma unroll
            for (int nt = 0; nt < 8; nt++) {
                int base = (wc*64 + nt*8 + qr)*ROWP32 + kk*8 + qc;
                b[nt][0] = Bs[base];        b[nt][1] = Bs[base + 4];
            }
            #pragma unroll
            for (int mt = 0; mt < 4; mt++)
                #pragma unroll
                for (int nt = 0; nt < 8; nt++)
                    mma16(c[mt][nt], a[mt], b[nt]);
        }
    }

    // epilogue: gu-col = wc*64 + nt*8 + qc*2 (+1); h = silu(g)*u
    __half* H = g_h + (size_t)(e * CAP + m0) * HID;
    #pragma unroll
    for (int mt = 0; mt < 4; mt++) {
        int r0 = wr*64 + mt*16 + qr;
        #pragma unroll
        for (int nt = 0; nt < 8; nt++) {
            int hcol = n0h + wc*32 + nt*4 + qc;
            float g0 = c[mt][nt][0], u0 = c[mt][nt][1];
            float g1 = c[mt][nt][2], u1 = c[mt][nt][3];
            H[(size_t)r0 * HID + hcol]       = __float2half_rn((g0 / (1.f + expf(-g0))) * u0);
            H[(size_t)(r0 + 8) * HID + hcol] = __float2half_rn((g1 / (1.f + expf(-g1))) * u1);
        }
    }
    #undef G1_ISSUE
}

// GEMM2: 128 slots x 128 out-dims, K=HID; y = x_token + D
__global__ __launch_bounds__(128, 2) void gemm2_tc(const __half* __restrict__ w2h,
                                                   const float* __restrict__ x) {
    int e = blockIdx.z;
    int m0 = blockIdx.y * 128;
    if (m0 >= g_count[e]) return;
    int n0 = blockIdx.x * 128;

    extern __shared__ uint32_t sm[];
    int tid = threadIdx.x;
    const __half* Ab = g_h + (size_t)(e * CAP + m0) * HID;
    const __half* Wb = w2h + (size_t)e * DIM * HID + (size_t)n0 * HID;

    #define G2_ISSUE(stage, chunk) do {                                        \
        uint32_t* As_ = sm + (stage) * STAGE_U32;                              \
        uint32_t* Bs_ = As_ + A_U32;                                           \
        int k0_ = (chunk) * 64;                                                \
        _Pragma("unroll")                                                      \
        for (int j = 0; j < 8; j++) {                                          \
            int fI = tid + 128*j; int row = fI >> 3, c8 = fI & 7;              \
            CP_ASYNC16(smem_u32(As_ + row*ROWP32 + c8*4),                      \
                       Ab + (size_t)row * HID + k0_ + c8*8);                   \
        }                                                                      \
        _Pragma("unroll")                                                      \
        for (int j = 0; j < 8; j++) {                                          \
            int fI = tid + 128*j; int r = fI >> 3, c8 = fI & 7;                \
            CP_ASYNC16(smem_u32(Bs_ + r*ROWP32 + c8*4),                        \
                       Wb + (size_t)r * HID + k0_ + c8*8);                     \
        }                                                                      \
    } while (0)

    float c[4][8][4];
    #pragma unroll
    for (int a = 0; a < 4; a++)
        #pragma unroll
        for (int b = 0; b < 8; b++)
            #pragma unroll
            for (int r = 0; r < 4; r++) c[a][b][r] = 0.f;

    int lane = tid & 31, wid = tid >> 5;
    int wr = wid >> 1, wc = wid & 1;
    int qr = lane >> 2, qc = lane & 3;

    G2_ISSUE(0, 0); CP_COMMIT();
    G2_ISSUE(1, 1); CP_COMMIT();

    const int NCH = HID / 64;   // 32
    for (int i = 0; i < NCH; i++) {
        int s = i % NSTAGE;
        CP_WAIT1();
        __syncthreads();
        if (i + 2 < NCH) G2_ISSUE((i + 2) % NSTAGE, i + 2);
        CP_COMMIT();
        const uint32_t* As = sm + s * STAGE_U32;
        const uint32_t* Bs = As + A_U32;
        #pragma unroll
        for (int kk = 0; kk < 4; kk++) {
            uint32_t a[4][4], b[8][2];
            #pragma unroll
            for (int mt = 0; mt < 4; mt++) {
                int base = (wr*64 + mt*16 + qr)*ROWP32 + kk*8 + qc;
                a[mt][0] = As[base];        a[mt][1] = As[base + 8*ROWP32];
                a[mt][2] = As[base + 4];    a[mt][3] = As[base + 8*ROWP32 + 4];
            }
            #pragma unroll
            for (int nt = 0; nt < 8; nt++) {
                int base = (wc*64 + nt*8 + qr)*ROWP32 + kk*8 + qc;
                b[nt][0] = Bs[base];        b[nt][1] = Bs[base + 4];
            }
            #pragma unroll
            for (int mt = 0; mt < 4; mt++)
                #pragma unroll
                for (int nt = 0; nt < 8; nt++)
                    mma16(c[mt][nt], a[mt], b[nt]);
        }
    }

    #pragma unroll
    for (int mt = 0; mt < 4; mt++) {
        int r0 = wr*64 + mt*16 + qr;
        int slot0 = e * CAP + m0 + r0;
        int slot1 = slot0 + 8;
        int t0 = g_slot_token[slot0];
        int t1 = g_slot_token[slot1];
        #pragma unroll
        for (int nt = 0; nt < 8; nt++) {
            int col = n0 + wc*64 + nt*8 + qc*2;
            float2 x0 = *(const float2*)&x[(size_t)t0 * DIM + col];
            float2 x1 = *(const float2*)&x[(size_t)t1 * DIM + col];
            float2 y0, y1;
            y0.x = x0.x + c[mt][nt][0];  y0.y = x0.y + c[mt][nt][1];
            y1.x = x1.x + c[mt][nt][2];  y1.y = x1.y + c[mt][nt][3];
            *(float2*)&g_y[(size_t)slot0 * DIM + col] = y0;
            *(float2*)&g_y[(size_t)slot1 * DIM + col] = y1;
        }
    }
    #undef G2_ISSUE
}

// ---------------- combine ----------------
__global__ __launch_bounds__(256) void combine_kernel(float* __restrict__ out) {
    int idx = blockIdx.x * 256 + threadIdx.x;
    if (idx >= N_TOK * DIM) return;
    int n = idx / DIM, d = idx - n * DIM;
    float r = 0.f;
    int s0 = g_assign_slot[2*n], s1 = g_assign_slot[2*n + 1];
    if (s0 >= 0) r += g_topk_w[2*n]     * g_y[(size_t)s0 * DIM + d];
    if (s1 >= 0) r += g_topk_w[2*n + 1] * g_y[(size_t)s1 * DIM + d];
    out[idx] = r;
}

// ---------------- launch ----------------
extern "C" void kernel_launch(void* const* d_in, const int* in_sizes, int n_in,
                              void* d_out, int out_size) {
    const float* x      = (const float*)d_in[0];
    const float* gate_w = (const float*)d_in[1];
    const float* w13    = (const float*)d_in[2];
    const float* w2     = (const float*)d_in[3];
    const float* norm_w = (const float*)d_in[4];
    float* out = (float*)d_out;

    cudaFuncSetAttribute(gemm1_tc, cudaFuncAttributeMaxDynamicSharedMemorySize, SMEM_BYTES);
    cudaFuncSetAttribute(gemm2_tc, cudaFuncAttributeMaxDynamicSharedMemorySize, SMEM_BYTES);

    __half* w13h; cudaGetSymbolAddress((void**)&w13h, g_w13h);
    __half* w2h;  cudaGetSymbolAddress((void**)&w2h,  g_w2h);

    cvt_half_kernel   <<<4096, 256>>>(w13, w13h, W13N/4);
    cvt_half_kernel   <<<4096, 256>>>(w2,  w2h,  W2N/4);
    router_kernel     <<<N_TOK/8, 256>>>(x, gate_w);
    disp_count_kernel <<<NSEG, 256>>>();
    disp_scan_kernel  <<<1, 32>>>();
    disp_assign_kernel<<<NSEG, 256>>>();
    prep_kernel       <<<NSLOT/8, 256>>>(x, norm_w);
    gemm1_tc          <<<dim3(HID/64, CAP/128, NEXP), 128, SMEM_BYTES>>>(w13h);
    gemm2_tc          <<<dim3(DIM/128, CAP/128, NEXP), 128, SMEM_BYTES>>>(w2h, x);
    combine_kernel    <<<(N_TOK*DIM + 255)/256, 256>>>(out);
}

// round 7
// speedup vs baseline: 7.7138x; 1.0049x over previous
#include <cuda_runtime.h>
#include <cuda_fp16.h>
#include <math.h>
#include <stdint.h>

// Problem constants
#define N_TOK 16384
#define DIM   768
#define NEXP  8
#define HID   2048
#define CAP   5120
#define NK    (N_TOK*2)
#define NSLOT (NEXP*CAP)
#define NSEG  64
#define SEGSZ (NK/NSEG)

#define W13N (NEXP*2*HID*DIM)
#define W2N  (NEXP*DIM*HID)

// ---------------- device scratch ----------------
__device__ int    g_topk_e[NK];
__device__ float  g_topk_w[NK];
__device__ int    g_count[NEXP];
__device__ int    g_slot_token[NSLOT];
__device__ float  g_slot_w[NSLOT];
__device__ int    g_seg_hist[NSEG][NEXP];
__device__ int    g_seg_base[NSEG][NEXP];
__device__ __half g_z[(size_t)NSLOT*DIM];
__device__ __half g_h[(size_t)NSLOT*HID];
__device__ __half g_w13h[W13N];
__device__ __half g_w2h[W2N];

// ---------------- helpers ----------------
__device__ __forceinline__ uint32_t smem_u32(const void* p) {
    uint32_t a;
    asm("{ .reg .u64 t; cvta.to.shared.u64 t, %1; cvt.u32.u64 %0, t; }" : "=r"(a) : "l"(p));
    return a;
}
#define CP_ASYNC16(s, g) \
    asm volatile("cp.async.cg.shared.global [%0], [%1], 16;" :: "r"(s), "l"(g))
#define CP_COMMIT() asm volatile("cp.async.commit_group;")
#define CP_WAIT1()  asm volatile("cp.async.wait_group 1;")

#define LDSM4(r0, r1, r2, r3, addr) \
    asm volatile("ldmatrix.sync.aligned.m8n8.x4.shared.b16 {%0,%1,%2,%3}, [%4];" \
        : "=r"(r0), "=r"(r1), "=r"(r2), "=r"(r3) : "r"(addr))

__device__ __forceinline__ void mma16(float* c, const uint32_t* a, const uint32_t* b) {
    asm("mma.sync.aligned.m16n8k16.row.col.f32.f16.f16.f32 "
        "{%0,%1,%2,%3}, {%4,%5,%6,%7}, {%8,%9}, {%0,%1,%2,%3};"
        : "+f"(c[0]), "+f"(c[1]), "+f"(c[2]), "+f"(c[3])
        : "r"(a[0]), "r"(a[1]), "r"(a[2]), "r"(a[3]), "r"(b[0]), "r"(b[1]));
}

// ---------------- weight f32 -> f16 ----------------
__global__ __launch_bounds__(256) void cvt_half_kernel(const float* __restrict__ src,
                                                       __half* __restrict__ dst, int n4) {
    int i = blockIdx.x * 256 + threadIdx.x;
    int stride = gridDim.x * 256;
    for (; i < n4; i += stride) {
        float4 v = ((const float4*)src)[i];
        __half2 h0 = __floats2half2_rn(v.x, v.y);
        __half2 h1 = __floats2half2_rn(v.z, v.w);
        uint2 pk;
        pk.x = *(uint32_t*)&h0;  pk.y = *(uint32_t*)&h1;
        ((uint2*)dst)[i] = pk;
    }
}

// ---------------- router ----------------
__global__ __launch_bounds__(256) void router_kernel(const float* __restrict__ x,
                                                     const float* __restrict__ gate_w) {
    __shared__ float gw[NEXP*DIM];
    int t = threadIdx.x;
    for (int i = t; i < NEXP*DIM; i += 256) gw[i] = gate_w[i];
    __syncthreads();
    int warp = t >> 5, lane = t & 31;
    int token = blockIdx.x * 8 + warp;
    const float* xr = x + (size_t)token * DIM;
    float acc[NEXP];
    #pragma unroll
    for (int e = 0; e < NEXP; e++) acc[e] = 0.f;
    #pragma unroll
    for (int i = 0; i < DIM/32; i++) {
        float xv = xr[lane + 32*i];
        #pragma unroll
        for (int e = 0; e < NEXP; e++) acc[e] += xv * gw[e*DIM + lane + 32*i];
    }
    #pragma unroll
    for (int e = 0; e < NEXP; e++) {
        #pragma unroll
        for (int off = 16; off; off >>= 1)
            acc[e] += __shfl_xor_sync(0xffffffffu, acc[e], off);
    }
    if (lane == 0) {
        int i0 = 0;
        #pragma unroll
        for (int e = 1; e < NEXP; e++) if (acc[e] > acc[i0]) i0 = e;
        int i1 = -1;
        #pragma unroll
        for (int e = 0; e < NEXP; e++) {
            if (e == i0) continue;
            if (i1 < 0 || acc[e] > acc[i1]) i1 = e;
        }
        float l0 = acc[i0], l1 = acc[i1];
        g_topk_e[2*token]   = i0;  g_topk_e[2*token+1] = i1;
        g_topk_w[2*token]   = 1.f / (1.f + expf(l1 - l0));
        g_topk_w[2*token+1] = 1.f / (1.f + expf(l0 - l1));
    }
}

// ---------------- dispatch ----------------
__global__ __launch_bounds__(256) void disp_count_kernel() {
    __shared__ int h[NEXP];
    int t = threadIdx.x, b = blockIdx.x;
    if (t < NEXP) h[t] = 0;
    __syncthreads();
    int2 ev = *(const int2*)(g_topk_e + b * SEGSZ + 2 * t);
    atomicAdd(&h[ev.x], 1);
    atomicAdd(&h[ev.y], 1);
    __syncthreads();
    if (t < NEXP) g_seg_hist[b][t] = h[t];
}

__global__ __launch_bounds__(32) void disp_scan_kernel() {
    int e = threadIdx.x;
    if (e >= NEXP) return;
    int run = 0;
    for (int s = 0; s < NSEG; s++) {
        g_seg_base[s][e] = run;
        run += g_seg_hist[s][e];
    }
    g_count[e] = run < CAP ? run : CAP;
}

__global__ __launch_bounds__(256) void disp_assign_kernel() {
    __shared__ int s[256][NEXP];
    int t = threadIdx.x, b = blockIdx.x;
    int idx0 = b * SEGSZ + 2 * t;
    int2 ev = *(const int2*)(g_topk_e + idx0);
    float2 wv = *(const float2*)(g_topk_w + idx0);

    int cnt[NEXP];
    #pragma unroll
    for (int e = 0; e < NEXP; e++) cnt[e] = (ev.x == e) + (ev.y == e);
    #pragma unroll
    for (int e = 0; e < NEXP; e++) s[t][e] = cnt[e];
    __syncthreads();
    for (int off = 1; off < 256; off <<= 1) {
        int v[NEXP];
        if (t >= off) {
            #pragma unroll
            for (int e = 0; e < NEXP; e++) v[e] = s[t - off][e];
        }
        __syncthreads();
        if (t >= off) {
            #pragma unroll
            for (int e = 0; e < NEXP; e++) s[t][e] += v[e];
        }
        __syncthreads();
    }
    int pos0 = 0, pos1 = 0;
    #pragma unroll
    for (int e = 0; e < NEXP; e++) {
        int pref = (t == 0 ? 0 : s[t-1][e]) + g_seg_base[b][e];
        if (ev.x == e) pos0 = pref;
        if (ev.y == e) pos1 = pref + (ev.x == e);
    }
    if (pos0 < CAP) {
        int slot = ev.x * CAP + pos0;
        g_slot_token[slot] = idx0 >> 1;
        g_slot_w[slot] = wv.x;
    }
    if (pos1 < CAP) {
        int slot = ev.y * CAP + pos1;
        g_slot_token[slot] = (idx0 + 1) >> 1;
        g_slot_w[slot] = wv.y;
    }
}

// ---------------- prep: z = half(RMSNorm(2x)*norm_w) ----------------
__global__ __launch_bounds__(256) void prep_kernel(const float* __restrict__ x,
                                                   const float* __restrict__ norm_w) {
    int warp = threadIdx.x >> 5, lane = threadIdx.x & 31;
    int slot = blockIdx.x * 8 + warp;
    int e = slot / CAP, c = slot % CAP;
    if (c >= g_count[e]) return;
    int token = g_slot_token[slot];
    const float* xr = x + (size_t)token * DIM;
    float xv[DIM/32];
    float ss = 0.f;
    #pragma unroll
    for (int i = 0; i < DIM/32; i++) { xv[i] = xr[lane + 32*i]; ss += xv[i]*xv[i]; }
    #pragma unroll
    for (int off = 16; off; off >>= 1) ss += __shfl_xor_sync(0xffffffffu, ss, off);
    float scale = 2.f * rsqrtf(4.f * ss / (float)DIM + 1e-6f);
    __half* zr = g_z + (size_t)slot * DIM;
    const float* nw = norm_w + e * DIM;
    #pragma unroll
    for (int i = 0; i < DIM/32; i++)
        zr[lane + 32*i] = __float2half_rn(xv[i] * scale * nw[lane + 32*i]);
}

// ---------------- fp16 mma.sync GEMMs with ldmatrix feeds ----------------
#define ROWP32  36
#define ROWB    (ROWP32*4)          // 144 bytes per row
#define A_U32   (128*ROWP32)
#define STAGE_U32 (2*A_U32)
#define NSTAGE  3
#define SMEM_BYTES (NSTAGE*STAGE_U32*4)   // 110592

// GEMM1: 128 slots x 128 gu-cols (=64 h-cols); B rows even=gate odd=up; K=DIM
__global__ __launch_bounds__(128, 2) void gemm1_tc(const __half* __restrict__ w13h) {
    int e = blockIdx.z;
    int m0 = blockIdx.y * 128;
    if (m0 >= g_count[e]) return;
    int n0h = blockIdx.x * 64;

    extern __shared__ uint32_t sm[];
    int tid = threadIdx.x;
    uint32_t smBase = smem_u32(sm);
    const __half* Ab = g_z + (size_t)(e * CAP + m0) * DIM;
    const __half* Wb = w13h + (size_t)e * 2 * HID * DIM;

    #define G1_ISSUE(stage, chunk) do {                                        \
        uint32_t* As_ = sm + (stage) * STAGE_U32;                              \
        uint32_t* Bs_ = As_ + A_U32;                                           \
        int k0_ = (chunk) * 64;                                                \
        _Pragma("unroll")                                                      \
        for (int j = 0; j < 8; j++) {                                          \
            int fI = tid + 128*j; int row = fI >> 3, c8 = fI & 7;              \
            CP_ASYNC16(smem_u32(As_ + row*ROWP32 + c8*4),                      \
                       Ab + (size_t)row * DIM + k0_ + c8*8);                   \
        }                                                                      \
        _Pragma("unroll")                                                      \
        for (int j = 0; j < 8; j++) {                                          \
            int fI = tid + 128*j; int r = fI >> 3, c8 = fI & 7;                \
            int gr = (r & 1) ? (HID + n0h + (r >> 1)) : (n0h + (r >> 1));      \
            CP_ASYNC16(smem_u32(Bs_ + r*ROWP32 + c8*4),                        \
                       Wb + (size_t)gr * DIM + k0_ + c8*8);                    \
        }                                                                      \
    } while (0)

    float c[4][8][4];
    #pragma unroll
    for (int a = 0; a < 4; a++)
        #pragma unroll
        for (int b = 0; b < 8; b++)
            #pragma unroll
            for (int r = 0; r < 4; r++) c[a][b][r] = 0.f;

    int lane = tid & 31, wid = tid >> 5;
    int wr = wid >> 1, wc = wid & 1;
    int qr = lane >> 2, qc = lane & 3;

    // ldmatrix lane offsets (bytes)
    uint32_t aLaneOff = (uint32_t)((lane & 15) * ROWB + (lane >> 4) * 16);
    uint32_t bLaneOff = (uint32_t)(((lane >> 4) * 8 + (lane & 7)) * ROWB + ((lane >> 3) & 1) * 16);

    G1_ISSUE(0, 0); CP_COMMIT();
    G1_ISSUE(1, 1); CP_COMMIT();

    const int NCH = DIM / 64;   // 12
    for (int i = 0; i < NCH; i++) {
        int s = i % NSTAGE;
        CP_WAIT1();
        __syncthreads();
        if (i + 2 < NCH) G1_ISSUE((i + 2) % NSTAGE, i + 2);
        CP_COMMIT();
        uint32_t aStage = smBase + (uint32_t)(s * STAGE_U32 * 4);
        uint32_t bStage = aStage + A_U32 * 4;
        #pragma unroll
        for (int kk = 0; kk < 4; kk++) {
            uint32_t a[4][4], b[8][2];
            #pragma unroll
            for (int mt = 0; mt < 4; mt++) {
                uint32_t ad = aStage + aLaneOff + (uint32_t)((wr*64 + mt*16) * ROWB) + kk*32;
                LDSM4(a[mt][0], a[mt][1], a[mt][2], a[mt][3], ad);
            }
            #pragma unroll
            for (int p = 0; p < 4; p++) {
                uint32_t bd = bStage + bLaneOff + (uint32_t)((wc*64 + p*16) * ROWB) + kk*32;
                LDSM4(b[2*p][0], b[2*p][1], b[2*p+1][0], b[2*p+1][1], bd);
            }
            #pragma unroll
            for (int mt = 0; mt < 4; mt++)
                #pragma unroll
                for (int nt = 0; nt < 8; nt++)
                    mma16(c[mt][nt], a[mt], b[nt]);
        }
    }

    __half* H = g_h + (size_t)(e * CAP + m0) * HID;
    #pragma unroll
    for (int mt = 0; mt < 4; mt++) {
        int r0 = wr*64 + mt*16 + qr;
        #pragma unroll
        for (int nt = 0; nt < 8; nt++) {
            int hcol = n0h + wc*32 + nt*4 + qc;
            float g0 = c[mt][nt][0], u0 = c[mt][nt][1];
            float g1 = c[mt][nt][2], u1 = c[mt][nt][3];
            H[(size_t)r0 * HID + hcol]       = __float2half_rn((g0 / (1.f + expf(-g0))) * u0);
            H[(size_t)(r0 + 8) * HID + hcol] = __float2half_rn((g1 / (1.f + expf(-g1))) * u1);
        }
    }
    #undef G1_ISSUE
}

// GEMM2 + fused combine: D = h @ w2^T; out[token] += cw * (x[token] + D)
__global__ __launch_bounds__(128, 2) void gemm2_tc(const __half* __restrict__ w2h,
                                                   const float* __restrict__ x,
                                                   float* __restrict__ out) {
    int e = blockIdx.z;
    int count = g_count[e];
    int m0 = blockIdx.y * 128;
    if (m0 >= count) return;
    int n0 = blockIdx.x * 128;

    extern __shared__ uint32_t sm[];
    int tid = threadIdx.x;
    uint32_t smBase = smem_u32(sm);
    const __half* Ab = g_h + (size_t)(e * CAP + m0) * HID;
    const __half* Wb = w2h + (size_t)e * DIM * HID + (size_t)n0 * HID;

    #define G2_ISSUE(stage, chunk) do {                                        \
        uint32_t* As_ = sm + (stage) * STAGE_U32;                              \
        uint32_t* Bs_ = As_ + A_U32;                                           \
        int k0_ = (chunk) * 64;                                                \
        _Pragma("unroll")                                                      \
        for (int j = 0; j < 8; j++) {                                          \
            int fI = tid + 128*j; int row = fI >> 3, c8 = fI & 7;              \
            CP_ASYNC16(smem_u32(As_ + row*ROWP32 + c8*4),                      \
                       Ab + (size_t)row * HID + k0_ + c8*8);                   \
        }                                                                      \
        _Pragma("unroll")                                                      \
        for (int j = 0; j < 8; j++) {                                          \
            int fI = tid + 128*j; int r = fI >> 3, c8 = fI & 7;                \
            CP_ASYNC16(smem_u32(Bs_ + r*ROWP32 + c8*4),                        \
                       Wb + (size_t)r * HID + k0_ + c8*8);                     \
        }                                                                      \
    } while (0)

    float c[4][8][4];
    #pragma unroll
    for (int a = 0; a < 4; a++)
        #pragma unroll
        for (int b = 0; b < 8; b++)
            #pragma unroll
            for (int r = 0; r < 4; r++) c[a][b][r] = 0.f;

    int lane = tid & 31, wid = tid >> 5;
    int wr = wid >> 1, wc = wid & 1;
    int qr = lane >> 2, qc = lane & 3;

    uint32_t aLaneOff = (uint32_t)((lane & 15) * ROWB + (lane >> 4) * 16);
    uint32_t bLaneOff = (uint32_t)(((lane >> 4) * 8 + (lane & 7)) * ROWB + ((lane >> 3) & 1) * 16);

    G2_ISSUE(0, 0); CP_COMMIT();
    G2_ISSUE(1, 1); CP_COMMIT();

    const int NCH = HID / 64;   // 32
    for (int i = 0; i < NCH; i++) {
        int s = i % NSTAGE;
        CP_WAIT1();
        __syncthreads();
        if (i + 2 < NCH) G2_ISSUE((i + 2) % NSTAGE, i + 2);
        CP_COMMIT();
        uint32_t aStage = smBase + (uint32_t)(s * STAGE_U32 * 4);
        uint32_t bStage = aStage + A_U32 * 4;
        #pragma unroll
        for (int kk = 0; kk < 4; kk++) {
            uint32_t a[4][4], b[8][2];
            #pragma unroll
            for (int mt = 0; mt < 4; mt++) {
                uint32_t ad = aStage + aLaneOff + (uint32_t)((wr*64 + mt*16) * ROWB) + kk*32;
                LDSM4(a[mt][0], a[mt][1], a[mt][2], a[mt][3], ad);
            }
            #pragma unroll
            for (int p = 0; p < 4; p++) {
                uint32_t bd = bStage + bLaneOff + (uint32_t)((wc*64 + p*16) * ROWB) + kk*32;
                LDSM4(b[2*p][0], b[2*p][1], b[2*p+1][0], b[2*p+1][1], bd);
            }
            #pragma unroll
            for (int mt = 0; mt < 4; mt++)
                #pragma unroll
                for (int nt = 0; nt < 8; nt++)
                    mma16(c[mt][nt], a[mt], b[nt]);
        }
    }

    // fused combine epilogue (guard rows beyond expert count)
    #pragma unroll
    for (int mt = 0; mt < 4; mt++) {
        int r0 = wr*64 + mt*16 + qr;
        int r1 = r0 + 8;
        bool v0 = (m0 + r0) < count;
        bool v1 = (m0 + r1) < count;
        int slot0 = e * CAP + m0 + r0;
        int slot1 = slot0 + 8;
        int t0 = v0 ? g_slot_token[slot0] : 0;
        int t1 = v1 ? g_slot_token[slot1] : 0;
        float cw0 = v0 ? g_slot_w[slot0] : 0.f;
        float cw1 = v1 ? g_slot_w[slot1] : 0.f;
        #pragma unroll
        for (int nt = 0; nt < 8; nt++) {
            int col = n0 + wc*64 + nt*8 + qc*2;
            if (v0) {
                float2 x0 = *(const float2*)&x[(size_t)t0 * DIM + col];
                atomicAdd(&out[(size_t)t0 * DIM + col],     cw0 * (x0.x + c[mt][nt][0]));
                atomicAdd(&out[(size_t)t0 * DIM + col + 1], cw0 * (x0.y + c[mt][nt][1]));
            }
            if (v1) {
                float2 x1 = *(const float2*)&x[(size_t)t1 * DIM + col];
                atomicAdd(&out[(size_t)t1 * DIM + col],     cw1 * (x1.x + c[mt][nt][2]));
                atomicAdd(&out[(size_t)t1 * DIM + col + 1], cw1 * (x1.y + c[mt][nt][3]));
            }
        }
    }
    #undef G2_ISSUE
}

// ---------------- launch ----------------
extern "C" void kernel_launch(void* const* d_in, const int* in_sizes, int n_in,
                              void* d_out, int out_size) {
    const float* x      = (const float*)d_in[0];
    const float* gate_w = (const float*)d_in[1];
    const float* w13    = (const float*)d_in[2];
    const float* w2     = (const float*)d_in[3];
    const float* norm_w = (const float*)d_in[4];
    float* out = (float*)d_out;

    cudaFuncSetAttribute(gemm1_tc, cudaFuncAttributeMaxDynamicSharedMemorySize, SMEM_BYTES);
    cudaFuncSetAttribute(gemm2_tc, cudaFuncAttributeMaxDynamicSharedMemorySize, SMEM_BYTES);

    __half* w13h; cudaGetSymbolAddress((void**)&w13h, g_w13h);
    __half* w2h;  cudaGetSymbolAddress((void**)&w2h,  g_w2h);

    cudaMemsetAsync(out, 0, (size_t)N_TOK * DIM * sizeof(float), 0);
    cvt_half_kernel   <<<4096, 256>>>(w13, w13h, W13N/4);
    cvt_half_kernel   <<<4096, 256>>>(w2,  w2h,  W2N/4);
    router_kernel     <<<N_TOK/8, 256>>>(x, gate_w);
    disp_count_kernel <<<NSEG, 256>>>();
    disp_scan_kernel  <<<1, 32>>>();
    disp_assign_kernel<<<NSEG, 256>>>();
    prep_kernel       <<<NSLOT/8, 256>>>(x, norm_w);
    gemm1_tc          <<<dim3(HID/64, CAP/128, NEXP), 128, SMEM_BYTES>>>(w13h);
    gemm2_tc          <<<dim3(DIM/128, CAP/128, NEXP), 128, SMEM_BYTES>>>(w2h, x, out);
}